// round 16
// baseline (speedup 1.0000x reference)
#include <cuda_runtime.h>
#include <cstdint>
#include <cmath>

// Problem constants (fixed by the reference)
#define D_MODEL   1024
#define NUM_HEADS 16
#define HEAD_DIM  64
#define B_SZ      2
#define SEQ       2048
#define M_TOT     (B_SZ * SEQ)   // 4096 rows for all projection GEMMs

// Scratch (allocation-free rule: __device__ globals). 4 x 16 MB = 64 MB.
__device__ float g_Q[(size_t)M_TOT * D_MODEL];
__device__ float g_K[(size_t)M_TOT * D_MODEL];
__device__ float g_V[(size_t)M_TOT * D_MODEL];
__device__ float g_C[(size_t)M_TOT * D_MODEL];

// ---------------------------------------------------------------------------
// tf32 / cp.async helpers
// ---------------------------------------------------------------------------
__device__ __forceinline__ float f2tf32(float x) {
    asm("cvt.rna.tf32.f32 %0, %0;" : "+f"(x));
    return x;
}

__device__ __forceinline__ void mma_tf32(float& c0, float& c1, float& c2, float& c3,
                                         float a0, float a1, float a2, float a3,
                                         float b0, float b1)
{
    asm volatile(
        "mma.sync.aligned.m16n8k8.row.col.f32.tf32.tf32.f32 "
        "{%0,%1,%2,%3}, {%4,%5,%6,%7}, {%8,%9}, {%0,%1,%2,%3};\n"
        : "+f"(c0), "+f"(c1), "+f"(c2), "+f"(c3)
        : "r"(__float_as_uint(a0)), "r"(__float_as_uint(a1)),
          "r"(__float_as_uint(a2)), "r"(__float_as_uint(a3)),
          "r"(__float_as_uint(b0)), "r"(__float_as_uint(b1)));
}

__device__ __forceinline__ void cp_async16(uint32_t dst, const void* src) {
    asm volatile("cp.async.cg.shared.global [%0], [%1], 16;\n" :: "r"(dst), "l"(src));
}
#define CP_COMMIT() asm volatile("cp.async.commit_group;\n" ::: "memory")
#define CP_WAIT(n)  asm volatile("cp.async.wait_group %0;\n" :: "n"(n) : "memory")

// ---------------------------------------------------------------------------
// GEMM + bias (tf32 tensor cores, cp.async 3-stage pipeline, 3 CTAs/SM)
//   Y[4096,1024] = X[4096,1024] @ W[1024,1024] + b
// CTA tile 128x128, BK=16, 128 threads = 4 warps (2m x 2n), warp tile 64x64.
// R16: all addressing strength-reduced to compile-time immediates:
//  - main loop unrolled 21x3 (+1 remainder) so the smem buffer index is a
//    compile-time constant -> LDS become [reg + imm];
//  - staging slots per thread differ by fixed strides (A: 32*K gmem /
//    32*AP smem; B: 4*N / 4*BPITCH) -> one gmem pointer per operand,
//    advanced by a constant per stage, everything else an immediate.
// A in [m][k], pitch 20 (banks 20r+c — conflict-free).
// B in [k][n], pitch 132 (banks 4c+r — conflict-free).
// ---------------------------------------------------------------------------
#define GEMM_M   4096
#define GEMM_N   1024
#define GEMM_K   1024
#define AP       20
#define BPITCH   132
#define A_STAGE  (128 * AP)     // 2560 floats
#define B_STAGE  (16 * BPITCH)  // 2112 floats
#define NSTAGE   3
#define GEMM_SMEM_FLOATS (NSTAGE * (A_STAGE + B_STAGE))   // 14016 -> 56064 B

// Issue one stage: 4 A chunks (thread rows aTm+32i) + 4 B chunks (k rows bTk+4i).
__device__ __forceinline__ void gemm_issue_sr(
    const float* aSrc, const float* bSrc, uint32_t aDst, uint32_t bDst)
{
    #pragma unroll
    for (int i = 0; i < 4; i++) {
        cp_async16(aDst + (uint32_t)(i * 32 * AP * 4),
                   aSrc + (size_t)i * 32 * GEMM_K);
        cp_async16(bDst + (uint32_t)(i * 4 * BPITCH * 4),
                   bSrc + (size_t)i * 4 * GEMM_N);
    }
}

__device__ __forceinline__ void gemm_compute16(
    const float* __restrict__ Ab, const float* __restrict__ Bb,
    float acc[4][8][4], int wm, int wn, int r, int c)
{
    #pragma unroll
    for (int s = 0; s < 2; s++) {
        const int kb = s * 8;
        float af[4][4], bf[8][2];
        #pragma unroll
        for (int mi = 0; mi < 4; mi++) {
            const int mb = wm + 16 * mi;
            af[mi][0] = f2tf32(Ab[(mb + r    ) * AP + kb + c    ]);
            af[mi][1] = f2tf32(Ab[(mb + r + 8) * AP + kb + c    ]);
            af[mi][2] = f2tf32(Ab[(mb + r    ) * AP + kb + c + 4]);
            af[mi][3] = f2tf32(Ab[(mb + r + 8) * AP + kb + c + 4]);
        }
        #pragma unroll
        for (int ni = 0; ni < 8; ni++) {
            const int nb = wn + 8 * ni;
            bf[ni][0] = f2tf32(Bb[(kb + c    ) * BPITCH + nb + r]);
            bf[ni][1] = f2tf32(Bb[(kb + c + 4) * BPITCH + nb + r]);
        }
        #pragma unroll
        for (int mi = 0; mi < 4; mi++)
            #pragma unroll
            for (int ni = 0; ni < 8; ni++)
                mma_tf32(acc[mi][ni][0], acc[mi][ni][1], acc[mi][ni][2], acc[mi][ni][3],
                         af[mi][0], af[mi][1], af[mi][2], af[mi][3],
                         bf[ni][0], bf[ni][1]);
    }
}

__device__ __forceinline__ void gemm_body(
    const float* __restrict__ X, const float* __restrict__ W,
    const float* __restrict__ bias, float* __restrict__ Y)
{
    extern __shared__ __align__(16) float gsm[];
    uint32_t smem_u32 = (uint32_t)__cvta_generic_to_shared(gsm);

    const int tid  = threadIdx.x;
    const int lane = tid & 31;
    const int warp = tid >> 5;           // 0..3
    const int wm   = (warp >> 1) * 64;
    const int wn   = (warp & 1) * 64;
    const int r    = lane >> 2;
    const int c    = lane & 3;

    const int m0 = blockIdx.y * 128;
    const int n0 = blockIdx.x * 128;

    float acc[4][8][4];
    #pragma unroll
    for (int i = 0; i < 4; i++)
        #pragma unroll
        for (int j = 0; j < 8; j++)
            #pragma unroll
            for (int q = 0; q < 4; q++) acc[i][j][q] = 0.f;

    // Staging maps (slot 0 of 4; others at fixed strides)
    const int aTm = tid >> 2;            // 0..31  (A row within first 32)
    const int aTk = (tid & 3) * 4;       // 0,4,8,12
    const int bTk = tid >> 5;            // 0..3   (B k-row within first 4)
    const int bTn = (tid & 31) * 4;      // 0..124

    const float* aSrc = X + (size_t)(m0 + aTm) * GEMM_K + aTk;
    const float* bSrc = W + (size_t)bTk * GEMM_N + n0 + bTn;
    const uint32_t aD = smem_u32 + (uint32_t)((aTm * AP + aTk) * 4);
    const uint32_t bD = smem_u32 +
        (uint32_t)((NSTAGE * A_STAGE + bTk * BPITCH + bTn) * 4);

    // prologue: stages 0 (k0=0) and 1 (k0=16) in flight
    gemm_issue_sr(aSrc, bSrc, aD, bD);
    CP_COMMIT();
    aSrc += 16; bSrc += (size_t)16 * GEMM_N;
    gemm_issue_sr(aSrc, bSrc, aD + (uint32_t)(A_STAGE * 4), bD + (uint32_t)(B_STAGE * 4));
    CP_COMMIT();
    aSrc += 16; bSrc += (size_t)16 * GEMM_N;

    // main: 63 iterations in 21 groups of 3 (buf == j, compile-time), then it=63
    for (int grp = 0; grp < 21; grp++) {
        #pragma unroll
        for (int j = 0; j < 3; j++) {
            const int it = grp * 3 + j;
            CP_WAIT(1);          // stage `it` landed
            __syncthreads();     // prev buf fully consumed by all threads

            if (it < 62) {       // prefetch stage it+2 -> buffer (j+2)%3
                const int pb = (j + 2) % 3;   // compile-time
                gemm_issue_sr(aSrc, bSrc,
                              aD + (uint32_t)(pb * A_STAGE * 4),
                              bD + (uint32_t)(pb * B_STAGE * 4));
                aSrc += 16; bSrc += (size_t)16 * GEMM_N;
            }
            CP_COMMIT();         // one group per iteration (may be empty)

            gemm_compute16(gsm + j * A_STAGE,
                           gsm + NSTAGE * A_STAGE + j * B_STAGE,
                           acc, wm, wn, r, c);
        }
    }
    // remainder: it = 63, buf 0
    CP_WAIT(0);
    __syncthreads();
    gemm_compute16(gsm, gsm + NSTAGE * A_STAGE, acc, wm, wn, r, c);

    // epilogue: add bias, write. c-frag layout: rows r, r+8; cols 2c, 2c+1.
    #pragma unroll
    for (int mi = 0; mi < 4; mi++) {
        const int m = m0 + wm + 16 * mi + r;
        #pragma unroll
        for (int ni = 0; ni < 8; ni++) {
            const int n = n0 + wn + 8 * ni + 2 * c;
            const float bx = bias[n], by = bias[n + 1];
            float2 o0 = make_float2(acc[mi][ni][0] + bx, acc[mi][ni][1] + by);
            float2 o1 = make_float2(acc[mi][ni][2] + bx, acc[mi][ni][3] + by);
            *(float2*)(Y + (size_t)m * GEMM_N + n)       = o0;
            *(float2*)(Y + (size_t)(m + 8) * GEMM_N + n) = o1;
        }
    }
}

__global__ __launch_bounds__(128, 3) void qkv_gemm_kernel(
    const float* __restrict__ x1, const float* __restrict__ x2,
    const float* __restrict__ Wq, const float* __restrict__ bq,
    const float* __restrict__ Wk, const float* __restrict__ bk,
    const float* __restrict__ Wv, const float* __restrict__ bv,
    float* __restrict__ Qp, float* __restrict__ Kp, float* __restrict__ Vp)
{
    const float *X, *W, *bias;
    float* Y;
    if (blockIdx.z == 0)      { X = x1; W = Wq; bias = bq; Y = Qp; }
    else if (blockIdx.z == 1) { X = x2; W = Wk; bias = bk; Y = Kp; }
    else                      { X = x2; W = Wv; bias = bv; Y = Vp; }
    gemm_body(X, W, bias, Y);
}

__global__ __launch_bounds__(128, 3) void out_gemm_kernel(
    const float* __restrict__ X, const float* __restrict__ W,
    const float* __restrict__ bias, float* __restrict__ Y)
{
    gemm_body(X, W, bias, Y);
}

// ---------------------------------------------------------------------------
// Flash attention, tf32 MMA, FA2 warp shape, KTILE=64, Q in registers,
// cp.async double-buffered K/V. (unchanged — proven at 543.3us)
// ---------------------------------------------------------------------------
#define QT      128
#define KTILE   64
#define KP      68
#define VP      72
#define PP      68

#define PS_OFF  0                          // 128*68 = 8704 floats
#define KS_OFF  8704                       // 2*64*68 = 8704
#define VS_OFF  (8704 + 8704)              // 2*64*72 = 9216
#define ATTN_SMEM_FLOATS (VS_OFF + 2 * KTILE * VP)   // 26624 floats = 106496 B

__device__ __forceinline__ void attn_issue_kv(
    uint32_t smem_u32, int buf, int kt, int tid,
    const float* __restrict__ K, const float* __restrict__ V, size_t base)
{
    #pragma unroll
    for (int i = 0; i < 8; i++) {
        const int idx  = i * 128 + tid;       // 1024 float4 slots per tile
        const int row  = idx >> 4;            // 0..63
        const int col4 = (idx & 15) * 4;      // 0..60
        const size_t g = base + (size_t)(kt * KTILE + row) * D_MODEL + col4;
        cp_async16(smem_u32 + (uint32_t)((KS_OFF + buf * (KTILE * KP) + row * KP + col4) * 4),
                   K + g);
        cp_async16(smem_u32 + (uint32_t)((VS_OFF + buf * (KTILE * VP) + row * VP + col4) * 4),
                   V + g);
    }
}

__global__ __launch_bounds__(128, 2) void attn_mma_kernel(
    const float* __restrict__ Q, const float* __restrict__ K,
    const float* __restrict__ V, float* __restrict__ O)
{
    extern __shared__ __align__(16) float sm[];
    float* Ps = sm + PS_OFF;
    uint32_t smem_u32 = (uint32_t)__cvta_generic_to_shared(sm);

    const int tid  = threadIdx.x;
    const int lane = tid & 31;
    const int warp = tid >> 5;    // 0..3
    const int r    = lane >> 2;   // fragment row group 0..7
    const int c    = lane & 3;    // fragment k/col group 0..3
    const int wq   = warp * 32;   // warp's 32-row Q strip

    const int q0 = blockIdx.x * QT;
    const int h  = blockIdx.y;
    const int b  = blockIdx.z;
    const size_t base = (size_t)b * SEQ * D_MODEL + (size_t)h * HEAD_DIM;

    // ---- load Q A-fragments directly from gmem into registers (once) ----
    float qreg[8][2][4];
    {
        const float* Qg = Q + base;
        #pragma unroll
        for (int kk = 0; kk < 8; kk++) {
            const int kb = kk * 8;
            #pragma unroll
            for (int mi = 0; mi < 2; mi++) {
                const int rb = q0 + wq + mi * 16;
                qreg[kk][mi][0] = f2tf32(Qg[(size_t)(rb + r    ) * D_MODEL + kb + c    ]);
                qreg[kk][mi][1] = f2tf32(Qg[(size_t)(rb + r + 8) * D_MODEL + kb + c    ]);
                qreg[kk][mi][2] = f2tf32(Qg[(size_t)(rb + r    ) * D_MODEL + kb + c + 4]);
                qreg[kk][mi][3] = f2tf32(Qg[(size_t)(rb + r + 8) * D_MODEL + kb + c + 4]);
            }
        }
    }

    float oacc[2][8][4];
    float mv[2][2], lv[2][2];
    #pragma unroll
    for (int mi = 0; mi < 2; mi++) {
        mv[mi][0] = -1e30f; mv[mi][1] = -1e30f;
        lv[mi][0] = 0.f;    lv[mi][1] = 0.f;
        #pragma unroll
        for (int i = 0; i < 8; i++)
            #pragma unroll
            for (int j = 0; j < 4; j++) oacc[mi][i][j] = 0.f;
    }

    const float scale = 0.125f;        // 1/sqrt(64)
    const int nTiles  = SEQ / KTILE;   // 32

    attn_issue_kv(smem_u32, 0, 0, tid, K, V, base);
    CP_COMMIT();

    for (int kt = 0; kt < nTiles; kt++) {
        const int buf = kt & 1;
        const float* Ks = sm + KS_OFF + buf * (KTILE * KP);
        const float* Vs = sm + VS_OFF + buf * (KTILE * VP);

        CP_WAIT(0);
        __syncthreads();

        if (kt + 1 < nTiles) {
            attn_issue_kv(smem_u32, buf ^ 1, kt + 1, tid, K, V, base);
            CP_COMMIT();
        }

        // ---- S = Q·K^T : 32 x 64 per warp; Q from registers ----
        float sacc[2][8][4];
        #pragma unroll
        for (int mi = 0; mi < 2; mi++)
            #pragma unroll
            for (int i = 0; i < 8; i++)
                #pragma unroll
                for (int j = 0; j < 4; j++) sacc[mi][i][j] = 0.f;

        #pragma unroll
        for (int kk = 0; kk < 8; kk++) {
            const int kb = kk * 8;
            #pragma unroll
            for (int nt = 0; nt < 8; nt++) {
                float b0 = f2tf32(Ks[(nt * 8 + r) * KP + kb + c    ]);
                float b1 = f2tf32(Ks[(nt * 8 + r) * KP + kb + c + 4]);
                #pragma unroll
                for (int mi = 0; mi < 2; mi++)
                    mma_tf32(sacc[mi][nt][0], sacc[mi][nt][1], sacc[mi][nt][2], sacc[mi][nt][3],
                             qreg[kk][mi][0], qreg[kk][mi][1],
                             qreg[kk][mi][2], qreg[kk][mi][3], b0, b1);
            }
        }

        // ---- online softmax per m-frag (rows r and r+8 within each) ----
        #pragma unroll
        for (int mi = 0; mi < 2; mi++) {
            float mx0 = -1e30f, mx1 = -1e30f;
            #pragma unroll
            for (int nt = 0; nt < 8; nt++) {
                sacc[mi][nt][0] *= scale; sacc[mi][nt][1] *= scale;
                sacc[mi][nt][2] *= scale; sacc[mi][nt][3] *= scale;
                mx0 = fmaxf(mx0, fmaxf(sacc[mi][nt][0], sacc[mi][nt][1]));
                mx1 = fmaxf(mx1, fmaxf(sacc[mi][nt][2], sacc[mi][nt][3]));
            }
            mx0 = fmaxf(mx0, __shfl_xor_sync(0xffffffffu, mx0, 1));
            mx0 = fmaxf(mx0, __shfl_xor_sync(0xffffffffu, mx0, 2));
            mx1 = fmaxf(mx1, __shfl_xor_sync(0xffffffffu, mx1, 1));
            mx1 = fmaxf(mx1, __shfl_xor_sync(0xffffffffu, mx1, 2));

            const float mn0 = fmaxf(mv[mi][0], mx0);
            const float mn1 = fmaxf(mv[mi][1], mx1);
            const float corr0 = __expf(mv[mi][0] - mn0);
            const float corr1 = __expf(mv[mi][1] - mn1);
            mv[mi][0] = mn0; mv[mi][1] = mn1;

            float rs0 = 0.f, rs1 = 0.f;
            #pragma unroll
            for (int nt = 0; nt < 8; nt++) {
                sacc[mi][nt][0] = __expf(sacc[mi][nt][0] - mn0);
                sacc[mi][nt][1] = __expf(sacc[mi][nt][1] - mn0);
                sacc[mi][nt][2] = __expf(sacc[mi][nt][2] - mn1);
                sacc[mi][nt][3] = __expf(sacc[mi][nt][3] - mn1);
                rs0 += sacc[mi][nt][0] + sacc[mi][nt][1];
                rs1 += sacc[mi][nt][2] + sacc[mi][nt][3];
            }
            rs0 += __shfl_xor_sync(0xffffffffu, rs0, 1);
            rs0 += __shfl_xor_sync(0xffffffffu, rs0, 2);
            rs1 += __shfl_xor_sync(0xffffffffu, rs1, 1);
            rs1 += __shfl_xor_sync(0xffffffffu, rs1, 2);

            lv[mi][0] = lv[mi][0] * corr0 + rs0;
            lv[mi][1] = lv[mi][1] * corr1 + rs1;
            #pragma unroll
            for (int nt = 0; nt < 8; nt++) {
                oacc[mi][nt][0] *= corr0; oacc[mi][nt][1] *= corr0;
                oacc[mi][nt][2] *= corr1; oacc[mi][nt][3] *= corr1;
            }

            const int rb = wq + mi * 16;
            #pragma unroll
            for (int nt = 0; nt < 8; nt++) {
                float2 p0 = make_float2(f2tf32(sacc[mi][nt][0]), f2tf32(sacc[mi][nt][1]));
                float2 p1 = make_float2(f2tf32(sacc[mi][nt][2]), f2tf32(sacc[mi][nt][3]));
                *(float2*)&Ps[(rb + r    ) * PP + nt * 8 + 2 * c] = p0;
                *(float2*)&Ps[(rb + r + 8) * PP + nt * 8 + 2 * c] = p1;
            }
        }
        __syncwarp();

        // ---- O += P·V ----
        #pragma unroll
        for (int kk = 0; kk < 8; kk++) {
            const int kb = kk * 8;
            float af[2][4];
            #pragma unroll
            for (int mi = 0; mi < 2; mi++) {
                const int rb = wq + mi * 16;
                af[mi][0] = Ps[(rb + r    ) * PP + kb + c    ];
                af[mi][1] = Ps[(rb + r + 8) * PP + kb + c    ];
                af[mi][2] = Ps[(rb + r    ) * PP + kb + c + 4];
                af[mi][3] = Ps[(rb + r + 8) * PP + kb + c + 4];
            }
            #pragma unroll
            for (int nt = 0; nt < 8; nt++) {
                float b0 = f2tf32(Vs[(kb + c    ) * VP + nt * 8 + r]);
                float b1 = f2tf32(Vs[(kb + c + 4) * VP + nt * 8 + r]);
                #pragma unroll
                for (int mi = 0; mi < 2; mi++)
                    mma_tf32(oacc[mi][nt][0], oacc[mi][nt][1], oacc[mi][nt][2], oacc[mi][nt][3],
                             af[mi][0], af[mi][1], af[mi][2], af[mi][3], b0, b1);
            }
        }
    }

    // ---- normalize and write context ----
    #pragma unroll
    for (int mi = 0; mi < 2; mi++) {
        const float inv0 = 1.0f / lv[mi][0];
        const float inv1 = 1.0f / lv[mi][1];
        const int rb = wq + mi * 16;
        #pragma unroll
        for (int nt = 0; nt < 8; nt++) {
            const int col = nt * 8 + 2 * c;
            float2 o0 = make_float2(oacc[mi][nt][0] * inv0, oacc[mi][nt][1] * inv0);
            float2 o1 = make_float2(oacc[mi][nt][2] * inv1, oacc[mi][nt][3] * inv1);
            *(float2*)(O + base + (size_t)(q0 + rb + r    ) * D_MODEL + col) = o0;
            *(float2*)(O + base + (size_t)(q0 + rb + r + 8) * D_MODEL + col) = o1;
        }
    }
}

// ---------------------------------------------------------------------------
// Launch: merged QKV projection -> attention -> output projection
// Inputs (metadata order): x1, x2, Wq, bq, Wk, bk, Wv, bv, Wo, bo
// ---------------------------------------------------------------------------
extern "C" void kernel_launch(void* const* d_in, const int* in_sizes, int n_in,
                              void* d_out, int out_size)
{
    (void)in_sizes; (void)n_in; (void)out_size;

    const float* x1 = (const float*)d_in[0];
    const float* x2 = (const float*)d_in[1];
    const float* Wq = (const float*)d_in[2];
    const float* bq = (const float*)d_in[3];
    const float* Wk = (const float*)d_in[4];
    const float* bk = (const float*)d_in[5];
    const float* Wv = (const float*)d_in[6];
    const float* bv = (const float*)d_in[7];
    const float* Wo = (const float*)d_in[8];
    const float* bo = (const float*)d_in[9];
    float* out = (float*)d_out;

    float *Qp, *Kp, *Vp, *Cp;
    cudaGetSymbolAddress((void**)&Qp, g_Q);
    cudaGetSymbolAddress((void**)&Kp, g_K);
    cudaGetSymbolAddress((void**)&Vp, g_V);
    cudaGetSymbolAddress((void**)&Cp, g_C);

    const int gemm_smem = GEMM_SMEM_FLOATS * (int)sizeof(float);   // 56064 B
    cudaFuncSetAttribute(qkv_gemm_kernel,
                         cudaFuncAttributeMaxDynamicSharedMemorySize, gemm_smem);
    cudaFuncSetAttribute(out_gemm_kernel,
                         cudaFuncAttributeMaxDynamicSharedMemorySize, gemm_smem);

    const int attn_smem = ATTN_SMEM_FLOATS * (int)sizeof(float);   // 106496 B
    cudaFuncSetAttribute(attn_mma_kernel,
                         cudaFuncAttributeMaxDynamicSharedMemorySize, attn_smem);

    dim3 qkv_grid(GEMM_N / 128, GEMM_M / 128, 3);   // (8, 32, 3)
    qkv_gemm_kernel<<<qkv_grid, 128, gemm_smem>>>(x1, x2, Wq, bq, Wk, bk, Wv, bv,
                                                  Qp, Kp, Vp);

    dim3 attn_grid(SEQ / QT, NUM_HEADS, B_SZ);      // (16, 16, 2)
    attn_mma_kernel<<<attn_grid, 128, attn_smem>>>(Qp, Kp, Vp, Cp);

    dim3 out_grid(GEMM_N / 128, GEMM_M / 128);      // (8, 32)
    out_gemm_kernel<<<out_grid, 128, gemm_smem>>>(Cp, Wo, bo, out);
}